// round 3
// baseline (speedup 1.0000x reference)
#include <cuda_runtime.h>
#include <stdint.h>

// Problem constants
#define IMGS 128          // 8 * 16 images
#define H 512
#define W 512
#define BINS 256          // 16 x 16 joint GLCM
#define SLABS 8           // row-slabs per image
#define RPS (H / SLABS)   // 64 rows per CTA
#define TPB 128           // 4 warps; each warp owns a 128-column strip
#define NWARP (TPB / 32)

#define FULLMASK 0xffffffffu

// Allocation-free scratch (statically zero-initialized; self-cleaning per run).
__device__ unsigned int g_counts[IMGS * BINS];
__device__ unsigned int g_tick[IMGS];
__device__ float        g_ent[IMGS];

// ---------------------------------------------------------------------------
// Kernel 1: GLCM histogram. Grid (SLABS, IMGS), TPB threads.
// Warp wq owns columns [wq*128, wq*128+128); walks RPS rows keeping the
// previous quantized row in registers (1 packed u32 per lane = 4 px).
// Pairs per pixel (i,j) matching jnp.roll semantics:
//   s0 = q[i, j-1], s1 = q[i-1, j+1], s2 = q[i-1, j], s3 = q[i-1, j-1]
// (indices wrapped mod 512). Last CTA per image computes entropy + self-zeroes.
// ---------------------------------------------------------------------------
__global__ __launch_bounds__(TPB) void glcm_hist_k(const float* __restrict__ x) {
    __shared__ unsigned int hist[NWARP][BINS];
    __shared__ float red[TPB];
    __shared__ int is_last_s;

    const int t   = threadIdx.x;
    const int wq  = t >> 5;
    const int ln  = t & 31;
    const int img = blockIdx.y;
    const float* __restrict__ base = x + (size_t)img * (H * W);

    // zero private histograms
    #pragma unroll
    for (int i = t; i < NWARP * BINS; i += TPB)
        (&hist[0][0])[i] = 0u;
    __syncthreads();

    unsigned int* __restrict__ hrow = hist[wq];

    const int r0  = blockIdx.x * RPS;
    const int c0  = wq * 128 + ln * 4;             // this lane's 4 columns
    const int jl  = (wq * 128 + W - 1) & (W - 1);  // col left of warp strip
    const int jr  = (wq * 128 + 128)   & (W - 1);  // col right of warp strip
    const int lnL = (ln + 31) & 31;
    const int lnR = (ln + 1)  & 31;

    // Prologue: quantize wrapped previous row (r0-1 mod H) into pp.
    unsigned pp;
    {
        const int ip = (r0 + H - 1) & (H - 1);
        float4 v = *(const float4*)(base + (size_t)ip * W + c0);
        int a0 = (int)(v.x * 15.0f);          // FMUL + trunc: bit-exact vs ref
        int a1 = (int)(v.y * 15.0f);
        int a2 = (int)(v.z * 15.0f);
        int a3 = (int)(v.w * 15.0f);
        pp = (unsigned)a0 | ((unsigned)a1 << 8) | ((unsigned)a2 << 16) | ((unsigned)a3 << 24);
    }

    for (int r = 0; r < RPS; r++) {
        const int i  = r0 + r;
        const int ip = (i + H - 1) & (H - 1);

        float4 v = *(const float4*)(base + (size_t)i * W + c0);
        const int q0 = (int)(v.x * 15.0f);
        const int q1 = (int)(v.y * 15.0f);
        const int q2 = (int)(v.z * 15.0f);
        const int q3 = (int)(v.w * 15.0f);
        const unsigned cc = (unsigned)q0 | ((unsigned)q1 << 8) |
                            ((unsigned)q2 << 16) | ((unsigned)q3 << 24);

        // Cross-lane neighbors (warp-strip edges patched by scalar loads).
        unsigned left_cur   = __shfl_sync(FULLMASK, cc >> 24, lnL);   // cur [c0-1]
        unsigned left_prev  = __shfl_sync(FULLMASK, pp >> 24, lnL);   // prev[c0-1]
        unsigned right_prev = __shfl_sync(FULLMASK, pp & 0xffu, lnR); // prev[c0+4]
        if (ln == 0) {
            left_cur  = (unsigned)(int)(base[(size_t)i  * W + jl] * 15.0f);
            left_prev = (unsigned)(int)(base[(size_t)ip * W + jl] * 15.0f);
        }
        if (ln == 31) {
            right_prev = (unsigned)(int)(base[(size_t)ip * W + jr] * 15.0f);
        }

        const unsigned p0 =  pp        & 0xffu;
        const unsigned p1 = (pp >> 8)  & 0xffu;
        const unsigned p2 = (pp >> 16) & 0xffu;
        const unsigned p3 =  pp >> 24;

        // px0: center q0, s = {left_cur, p1, p0, left_prev}
        {
            const unsigned b = (unsigned)q0 << 4;
            atomicAdd(&hrow[b + left_cur ], 1u);
            atomicAdd(&hrow[b + p1       ], 1u);
            atomicAdd(&hrow[b + p0       ], 1u);
            atomicAdd(&hrow[b + left_prev], 1u);
        }
        // px1: center q1, s = {q0, p2, p1, p0}
        {
            const unsigned b = (unsigned)q1 << 4;
            atomicAdd(&hrow[b + (unsigned)q0], 1u);
            atomicAdd(&hrow[b + p2], 1u);
            atomicAdd(&hrow[b + p1], 1u);
            atomicAdd(&hrow[b + p0], 1u);
        }
        // px2: center q2, s = {q1, p3, p2, p1}
        {
            const unsigned b = (unsigned)q2 << 4;
            atomicAdd(&hrow[b + (unsigned)q1], 1u);
            atomicAdd(&hrow[b + p3], 1u);
            atomicAdd(&hrow[b + p2], 1u);
            atomicAdd(&hrow[b + p1], 1u);
        }
        // px3: center q3, s = {q2, right_prev, p3, p2}
        {
            const unsigned b = (unsigned)q3 << 4;
            atomicAdd(&hrow[b + (unsigned)q2 ], 1u);
            atomicAdd(&hrow[b + right_prev   ], 1u);
            atomicAdd(&hrow[b + p3           ], 1u);
            atomicAdd(&hrow[b + p2           ], 1u);
        }

        pp = cc;
    }

    // Flush: sum warp copies -> per-image global bins (2 bins per thread).
    __syncthreads();
    #pragma unroll
    for (int b = t; b < BINS; b += TPB) {
        unsigned s = 0u;
        #pragma unroll
        for (int wI = 0; wI < NWARP; wI++) s += hist[wI][b];
        atomicAdd(&g_counts[img * BINS + b], s);
    }

    // Last-CTA-per-image: compute entropy, self-zero counts + ticket.
    __threadfence();
    if (t == 0) {
        unsigned tk = atomicAdd(&g_tick[img], 1u);
        is_last_s = (tk == SLABS - 1);
    }
    __syncthreads();
    if (!is_last_s) return;
    __threadfence();

    // Each thread handles bins t and t+128.
    const float inv_total = 1.0f / (4.0f * H * W);
    float acc = 0.0f;
    #pragma unroll
    for (int b = t; b < BINS; b += TPB) {
        const float p = (float)g_counts[img * BINS + b] * inv_total;
        acc += -p * logf(p + 1e-10f);
        g_counts[img * BINS + b] = 0u;   // self-clean for next replay
    }
    red[t] = acc;
    __syncthreads();
    #pragma unroll
    for (int s = TPB / 2; s > 0; s >>= 1) {
        if (t < s) red[t] += red[t + s];
        __syncthreads();
    }
    if (t == 0) {
        g_ent[img]  = red[0];
        g_tick[img] = 0u;                // self-clean ticket
    }
}

// ---------------------------------------------------------------------------
// Kernel 2: broadcast entropy. 4 CTAs per image, 256 threads each.
// ---------------------------------------------------------------------------
__global__ __launch_bounds__(256) void bcast_k(float* __restrict__ out) {
    const int img  = blockIdx.x >> 2;
    const int part = blockIdx.x & 3;
    const float e  = g_ent[img];
    const float4 val = make_float4(e, e, e, e);

    float4* o = (float4*)(out + (size_t)img * (H * W) + (size_t)part * (H * W / 4));
    #pragma unroll 4
    for (int k = threadIdx.x; k < (H * W / 4) / 4; k += 256)   // 16384 float4/part
        o[k] = val;
}

// ---------------------------------------------------------------------------
// Launch: histogram(+entropy tail) -> broadcast. 2 launches, graph-capturable.
// ---------------------------------------------------------------------------
extern "C" void kernel_launch(void* const* d_in, const int* in_sizes, int n_in,
                              void* d_out, int out_size) {
    const float* x = (const float*)d_in[0];
    float* out = (float*)d_out;
    (void)in_sizes; (void)n_in; (void)out_size;

    dim3 g(SLABS, IMGS);
    glcm_hist_k<<<g, TPB>>>(x);
    bcast_k<<<IMGS * 4, 256>>>(out);
}

// round 4
// speedup vs baseline: 1.0016x; 1.0016x over previous
#include <cuda_runtime.h>
#include <stdint.h>

// Problem constants
#define IMGS 128          // 8 * 16 images
#define H 512
#define W 512
#define BINS 256          // 16 x 16 joint GLCM
#define SLABS 8           // row-slabs per image (= CTAs per image)
#define RPS (H / SLABS)   // 64 rows per CTA
#define TPB 128           // 4 warps; each warp owns a 128-column strip
#define NWARP (TPB / 32)

#define FULLMASK 0xffffffffu

// Allocation-free scratch (statically zero-initialized; self-cleaning per run).
__device__ unsigned int g_counts[IMGS * BINS];
__device__ unsigned int g_tick[IMGS];    // pre-entropy ticket
__device__ unsigned int g_tick2[IMGS];   // post-broadcast cleanup ticket
__device__ unsigned int g_done[IMGS];    // entropy-ready flag
__device__ float        g_ent[IMGS];

// ---------------------------------------------------------------------------
// Fused kernel: GLCM histogram + entropy + broadcast. Grid (SLABS, IMGS).
// __launch_bounds__(TPB, 8): guarantees >=8 CTAs/SM resident => all 1024 CTAs
// of the grid are co-resident (148*8 = 1184 slots), making the per-image
// spin-wait deadlock-free.
//
// Pairs per pixel (i,j), matching jnp.roll semantics:
//   s0 = q[i, j-1], s1 = q[i-1, j+1], s2 = q[i-1, j], s3 = q[i-1, j-1]
// (indices wrapped mod 512).
// ---------------------------------------------------------------------------
__global__ __launch_bounds__(TPB, 8) void glcm_fused_k(const float* __restrict__ x,
                                                       float* __restrict__ out) {
    __shared__ unsigned int hist[NWARP][BINS];
    __shared__ float red[TPB];
    __shared__ int is_last_s;

    const int t   = threadIdx.x;
    const int wq  = t >> 5;
    const int ln  = t & 31;
    const int img = blockIdx.y;
    const float* __restrict__ base = x + (size_t)img * (H * W);

    // zero private histograms
    #pragma unroll
    for (int i = t; i < NWARP * BINS; i += TPB)
        (&hist[0][0])[i] = 0u;
    __syncthreads();

    unsigned int* __restrict__ hrow = hist[wq];

    const int r0  = blockIdx.x * RPS;
    const int c0  = wq * 128 + ln * 4;             // this lane's 4 columns
    const int jl  = (wq * 128 + W - 1) & (W - 1);  // col left of warp strip
    const int jr  = (wq * 128 + 128)   & (W - 1);  // col right of warp strip
    const int lnL = (ln + 31) & 31;
    const int lnR = (ln + 1)  & 31;

    // Prologue: quantize wrapped previous row (r0-1 mod H) into pp.
    unsigned pp;
    {
        const int ip = (r0 + H - 1) & (H - 1);
        float4 v = *(const float4*)(base + (size_t)ip * W + c0);
        int a0 = (int)(v.x * 15.0f);          // FMUL + trunc: bit-exact vs ref
        int a1 = (int)(v.y * 15.0f);
        int a2 = (int)(v.z * 15.0f);
        int a3 = (int)(v.w * 15.0f);
        pp = (unsigned)a0 | ((unsigned)a1 << 8) | ((unsigned)a2 << 16) | ((unsigned)a3 << 24);
    }

    for (int r = 0; r < RPS; r++) {
        const int i  = r0 + r;
        const int ip = (i + H - 1) & (H - 1);

        float4 v = *(const float4*)(base + (size_t)i * W + c0);
        const int q0 = (int)(v.x * 15.0f);
        const int q1 = (int)(v.y * 15.0f);
        const int q2 = (int)(v.z * 15.0f);
        const int q3 = (int)(v.w * 15.0f);
        const unsigned cc = (unsigned)q0 | ((unsigned)q1 << 8) |
                            ((unsigned)q2 << 16) | ((unsigned)q3 << 24);

        // Cross-lane neighbors (warp-strip edges patched by scalar loads).
        unsigned left_cur   = __shfl_sync(FULLMASK, cc >> 24, lnL);   // cur [c0-1]
        unsigned left_prev  = __shfl_sync(FULLMASK, pp >> 24, lnL);   // prev[c0-1]
        unsigned right_prev = __shfl_sync(FULLMASK, pp & 0xffu, lnR); // prev[c0+4]
        if (ln == 0) {
            left_cur  = (unsigned)(int)(base[(size_t)i  * W + jl] * 15.0f);
            left_prev = (unsigned)(int)(base[(size_t)ip * W + jl] * 15.0f);
        }
        if (ln == 31) {
            right_prev = (unsigned)(int)(base[(size_t)ip * W + jr] * 15.0f);
        }

        const unsigned p0 =  pp        & 0xffu;
        const unsigned p1 = (pp >> 8)  & 0xffu;
        const unsigned p2 = (pp >> 16) & 0xffu;
        const unsigned p3 =  pp >> 24;

        // px0: center q0, s = {left_cur, p1, p0, left_prev}
        {
            const unsigned b = (unsigned)q0 << 4;
            atomicAdd(&hrow[b + left_cur ], 1u);
            atomicAdd(&hrow[b + p1       ], 1u);
            atomicAdd(&hrow[b + p0       ], 1u);
            atomicAdd(&hrow[b + left_prev], 1u);
        }
        // px1: center q1, s = {q0, p2, p1, p0}
        {
            const unsigned b = (unsigned)q1 << 4;
            atomicAdd(&hrow[b + (unsigned)q0], 1u);
            atomicAdd(&hrow[b + p2], 1u);
            atomicAdd(&hrow[b + p1], 1u);
            atomicAdd(&hrow[b + p0], 1u);
        }
        // px2: center q2, s = {q1, p3, p2, p1}
        {
            const unsigned b = (unsigned)q2 << 4;
            atomicAdd(&hrow[b + (unsigned)q1], 1u);
            atomicAdd(&hrow[b + p3], 1u);
            atomicAdd(&hrow[b + p2], 1u);
            atomicAdd(&hrow[b + p1], 1u);
        }
        // px3: center q3, s = {q2, right_prev, p3, p2}
        {
            const unsigned b = (unsigned)q3 << 4;
            atomicAdd(&hrow[b + (unsigned)q2 ], 1u);
            atomicAdd(&hrow[b + right_prev   ], 1u);
            atomicAdd(&hrow[b + p3           ], 1u);
            atomicAdd(&hrow[b + p2           ], 1u);
        }

        pp = cc;
    }

    // Flush: sum warp copies -> per-image global bins (2 bins per thread).
    __syncthreads();
    #pragma unroll
    for (int b = t; b < BINS; b += TPB) {
        unsigned s = 0u;
        #pragma unroll
        for (int wI = 0; wI < NWARP; wI++) s += hist[wI][b];
        atomicAdd(&g_counts[img * BINS + b], s);
    }

    // Ticket: last CTA of this image computes entropy; others spin.
    __threadfence();
    if (t == 0) {
        unsigned tk = atomicAdd(&g_tick[img], 1u);
        is_last_s = (tk == SLABS - 1);
    }
    __syncthreads();

    if (is_last_s) {
        __threadfence();   // acquire: all 8 CTAs' flushes visible
        const float inv_total = 1.0f / (4.0f * H * W);
        float acc = 0.0f;
        #pragma unroll
        for (int b = t; b < BINS; b += TPB) {
            const float p = (float)g_counts[img * BINS + b] * inv_total;
            acc += -p * logf(p + 1e-10f);
            g_counts[img * BINS + b] = 0u;   // self-clean for next replay
        }
        red[t] = acc;
        __syncthreads();
        #pragma unroll
        for (int s = TPB / 2; s > 0; s >>= 1) {
            if (t < s) red[t] += red[t + s];
            __syncthreads();
        }
        if (t == 0) {
            g_ent[img] = red[0];
            __threadfence();               // release g_ent before flag
            g_done[img] = 1u;
        }
        __syncthreads();
    } else {
        if (t == 0) {
            while (((volatile unsigned*)g_done)[img] == 0u) __nanosleep(64);
        }
        __syncthreads();
        __threadfence();                   // acquire g_ent
    }

    // Broadcast: each CTA writes its own 64-row slab (128 KB, contiguous).
    const float e = g_ent[img];
    const float4 val = make_float4(e, e, e, e);
    float4* __restrict__ o = (float4*)(out + (size_t)img * (H * W) + (size_t)r0 * W);
    #pragma unroll 8
    for (int k = t; k < RPS * W / 4; k += TPB)   // 8192 float4 per slab
        o[k] = val;

    // Cleanup ticket: last CTA past broadcast resets per-image state.
    __threadfence();
    if (t == 0) {
        unsigned f = atomicAdd(&g_tick2[img], 1u);
        if (f == SLABS - 1) {
            g_tick[img]  = 0u;
            g_tick2[img] = 0u;
            g_done[img]  = 0u;
        }
    }
}

// ---------------------------------------------------------------------------
// Launch: one fused kernel, graph-capturable.
// ---------------------------------------------------------------------------
extern "C" void kernel_launch(void* const* d_in, const int* in_sizes, int n_in,
                              void* d_out, int out_size) {
    const float* x = (const float*)d_in[0];
    float* out = (float*)d_out;
    (void)in_sizes; (void)n_in; (void)out_size;

    dim3 g(SLABS, IMGS);
    glcm_fused_k<<<g, TPB>>>(x, out);
}